// round 5
// baseline (speedup 1.0000x reference)
#include <cuda_runtime.h>
#include <cstdint>

// ---------------- problem constants ----------------
#define C_IN   256
#define C_OUT  256
#define PIXN   16384          // 64*256 pixels per (tensor, batch)
#define HOUTN  768
#define WwN    256

// ---------------- tiling ----------------
// CTA: 256 out-ch x 128 pixels, K in chunks of 32. 8 warps, each 64(out) x 64(pix).
#define KB      32
#define NKS     4             // k-steps of 8 per chunk
#define NCHUNK  8
#define RPX     136           // X row stride (floats): 136 % 32 == 8 -> conflict-free B frags
#define W_STAGE 32768         // 256 m x 32 k x 4B, fragment-packed
#define X_STAGE (KB*RPX*4)    // 17408 B
#define STAGE_B (W_STAGE + X_STAGE)
#define NSTAGE  3
#define SMEM_BYTES (NSTAGE * STAGE_B)   // 150528

// W fragment-packed: float4 slot index within chunk = (mb16*4 + ksi)*32 + lane
__device__ float g_Wp[C_IN * C_OUT];

struct XPtrs { const float* p[12]; };

__device__ __forceinline__ uint32_t f2tf32(float v) {
    uint32_t r; asm("cvt.rna.tf32.f32 %0, %1;" : "=r"(r) : "f"(v)); return r;
}
__device__ __forceinline__ void mma_tf32(float& d0, float& d1, float& d2, float& d3,
                                         uint32_t a0, uint32_t a1, uint32_t a2, uint32_t a3,
                                         uint32_t b0, uint32_t b1) {
    asm volatile(
        "mma.sync.aligned.m16n8k8.row.col.f32.tf32.tf32.f32 "
        "{%0,%1,%2,%3},{%4,%5,%6,%7},{%8,%9},{%0,%1,%2,%3};"
        : "+f"(d0), "+f"(d1), "+f"(d2), "+f"(d3)
        : "r"(a0), "r"(a1), "r"(a2), "r"(a3), "r"(b0), "r"(b1));
}
__device__ __forceinline__ void cp16(void* s, const float* g) {
    uint32_t sa = (uint32_t)__cvta_generic_to_shared(s);
    asm volatile("cp.async.cg.shared.global [%0], [%1], 16;\n" :: "r"(sa), "l"(g));
}

// ---- pre-kernel: pack W[c][o] into per-thread tf32 fragment quads ----
// packed float index t: j=t&3, lane=(t>>2)&31, ksi=(t>>7)&3, mb16=(t>>9)&15, kc=t>>13
// A-quad of thread lane at (kc,mb16,ksi): {W[k][m], W[k][m+8], W[k+4][m], W[k+4][m+8]}
__global__ void wpack_kernel(const float* __restrict__ W) {
    int t    = blockIdx.x * 256 + threadIdx.x;
    int j    = t & 3;
    int lane = (t >> 2) & 31;
    int ksi  = (t >> 7) & 3;
    int mb16 = (t >> 9) & 15;
    int kc   = t >> 13;
    int gid = lane >> 2, tig = lane & 3;
    int m = mb16 * 16 + gid + (j & 1) * 8;
    int k = kc * KB + ksi * 8 + tig + (j >> 1) * 4;
    g_Wp[t] = __uint_as_float(f2tf32(W[k * C_OUT + m]));
}

// ---- main kernel ----
__global__ void __launch_bounds__(256, 1)
conv_interleave_kernel(XPtrs xs, const float* __restrict__ bg, float* __restrict__ out)
{
    extern __shared__ char smem[];

    const int tid  = threadIdx.x;
    const int lane = tid & 31;
    const int warp = tid >> 5;
    const int gid  = lane >> 2;
    const int tig  = lane & 3;

    const int p0 = blockIdx.x * 128;
    const int z  = blockIdx.y;              // 0..23
    const int ii = z >> 1;
    const int bb = z & 1;
    const float* Xg = xs.p[ii] + (size_t)bb * (C_IN * PIXN);

    const int warp_m  = (warp >> 1) * 64;   // out-channel base of warp tile
    const int wm16    = (warp >> 1) * 4;    // m16-block base
    const int warp_n  = (warp & 1) * 64;    // pixel base of warp tile

    float d[4][8][4];
    #pragma unroll
    for (int mb = 0; mb < 4; ++mb)
        #pragma unroll
        for (int nb = 0; nb < 8; ++nb)
            #pragma unroll
            for (int r = 0; r < 4; ++r) d[mb][nb][r] = 0.0f;

    // ---- stage loader ----
    auto load_stage = [&](int ch) {
        const int st = ch % NSTAGE;
        char* wdst = smem + st * STAGE_B;
        char* xdst = wdst + W_STAGE;
        const float* wsrc = g_Wp + ch * (KB * C_OUT);
        #pragma unroll
        for (int it = 0; it < 8; ++it) {           // 2048 x 16B, fully linear
            int idx = it * 256 + tid;
            cp16(wdst + idx * 16, wsrc + idx * 4);
        }
        #pragma unroll
        for (int it = 0; it < 4; ++it) {           // X chunk: 32 rows x 512B (row pad 544B)
            int idx = it * 256 + tid;
            int k = idx >> 5, q = idx & 31;
            cp16(xdst + k * (RPX * 4) + q * 16,
                 Xg + (size_t)(ch * KB + k) * PIXN + p0 + q * 4);
        }
        asm volatile("cp.async.commit_group;");
    };

    load_stage(0);
    load_stage(1);

    #pragma unroll 1
    for (int ch = 0; ch < NCHUNK; ++ch) {
        asm volatile("cp.async.wait_group 1;");
        __syncthreads();

        const int s = ch % NSTAGE;
        if (ch + 2 < NCHUNK) load_stage(ch + 2);

        const float4* Wf4 = (const float4*)(smem + s * STAGE_B);
        const float*  Xst = (const float*)(smem + s * STAGE_B + W_STAGE);

        // fragment register double-buffers
        float4 afr[2][4];
        float  bfr[2][16];

        auto ldfrag = [&](int ksi, float4* areg, float* breg) {
            #pragma unroll
            for (int mb = 0; mb < 4; ++mb)
                areg[mb] = Wf4[((wm16 + mb) * 4 + ksi) * 32 + lane];
            const int kr = ksi * 8 + tig;
            #pragma unroll
            for (int nb = 0; nb < 8; ++nb) {
                const int n = warp_n + nb * 8 + gid;
                breg[2 * nb]     = Xst[kr * RPX + n];
                breg[2 * nb + 1] = Xst[(kr + 4) * RPX + n];
            }
        };

        ldfrag(0, afr[0], bfr[0]);

        #pragma unroll
        for (int ksi = 0; ksi < NKS; ++ksi) {
            const int cur = ksi & 1;
            if (ksi + 1 < NKS) ldfrag(ksi + 1, afr[cur ^ 1], bfr[cur ^ 1]);

            uint32_t bt[16];
            #pragma unroll
            for (int i = 0; i < 16; ++i) bt[i] = f2tf32(bfr[cur][i]);

            #pragma unroll
            for (int mb = 0; mb < 4; ++mb) {
                const uint32_t a0 = __float_as_uint(afr[cur][mb].x);
                const uint32_t a1 = __float_as_uint(afr[cur][mb].y);
                const uint32_t a2 = __float_as_uint(afr[cur][mb].z);
                const uint32_t a3 = __float_as_uint(afr[cur][mb].w);
                #pragma unroll
                for (int nb = 0; nb < 8; ++nb)
                    mma_tf32(d[mb][nb][0], d[mb][nb][1], d[mb][nb][2], d[mb][nb][3],
                             a0, a1, a2, a3, bt[2 * nb], bt[2 * nb + 1]);
            }
        }
        __syncthreads();   // all warps done with stage s before it is refilled
    }

    // ---- epilogue: interleaved scatter + bias*count ----
    #pragma unroll
    for (int mb = 0; mb < 4; ++mb) {
        const int o = warp_m + mb * 16 + gid;
        const float bv0 = __ldg(bg + o);
        const float bv1 = __ldg(bg + o + 8);
        #pragma unroll
        for (int nb = 0; nb < 8; ++nb) {
            const int p = p0 + warp_n + nb * 8 + 2 * tig;
            const int h = p >> 8;
            const int w = p & 255;
            const int r = 12 * h + ii;
            const int cnt = min(11, r) - max(0, r - (HOUTN - 12)) + 1;
            const float fc = (float)cnt;
            const float bias0 = bv0 * fc;
            const float bias1 = bv1 * fc;
            const size_t base = ((size_t)(bb * C_OUT + o) * HOUTN + r) * WwN + w;
            float2 v0 = make_float2(d[mb][nb][0] + bias0, d[mb][nb][1] + bias0);
            float2 v1 = make_float2(d[mb][nb][2] + bias1, d[mb][nb][3] + bias1);
            *reinterpret_cast<float2*>(out + base) = v0;
            *reinterpret_cast<float2*>(out + base + (size_t)8 * HOUTN * WwN) = v1;
        }
    }
}

extern "C" void kernel_launch(void* const* d_in, const int* in_sizes, int n_in,
                              void* d_out, int out_size)
{
    (void)in_sizes; (void)n_in; (void)out_size;

    XPtrs xs;
    for (int i = 0; i < 12; ++i) xs.p[i] = (const float*)d_in[i];
    const float* W = (const float*)d_in[12];
    const float* b = (const float*)d_in[13];
    float* out = (float*)d_out;

    wpack_kernel<<<256, 256>>>(W);

    cudaFuncSetAttribute(conv_interleave_kernel,
                         cudaFuncAttributeMaxDynamicSharedMemorySize, SMEM_BYTES);
    dim3 grid(PIXN / 128, 24, 1);   // 128 x 24 = 3072 CTAs
    conv_interleave_kernel<<<grid, 256, SMEM_BYTES>>>(xs, b, out);
}

// round 6
// speedup vs baseline: 1.4613x; 1.4613x over previous
#include <cuda_runtime.h>
#include <cstdint>

// ---------------- problem constants ----------------
#define C_IN   256
#define C_OUT  256
#define PIXN   16384          // 64*256 pixels per (tensor, batch)
#define HOUTN  768
#define WwN    256

// ---------------- tiling ----------------
// CTA: 256 out-ch x 128 pixels, K chunks of 32. 16 warps (512 thr), warp tile 64x32.
#define KB      32
#define NKS     4             // k-steps of 8 per chunk
#define NCHUNK  8
#define RPX     136           // X row stride floats: 136 % 32 == 8 -> conflict-free B frags
#define W_STAGE 32768         // fragment-packed W chunk: 256 m x 32 k x 4B
#define X_STAGE (KB*RPX*4)    // 17408 B
#define STAGE_B (W_STAGE + X_STAGE)
#define NSTAGE  3
#define SMEM_BYTES (NSTAGE * STAGE_B)   // 150528

// W fragment-packed: float4 slot within chunk = (mb16*4 + ksi)*32 + lane
__device__ float g_Wp[C_IN * C_OUT];

struct XPtrs { const float* p[12]; };

__device__ __forceinline__ uint32_t f2tf32(float v) {
    uint32_t r; asm("cvt.rna.tf32.f32 %0, %1;" : "=r"(r) : "f"(v)); return r;
}
__device__ __forceinline__ void mma_tf32(float& d0, float& d1, float& d2, float& d3,
                                         uint32_t a0, uint32_t a1, uint32_t a2, uint32_t a3,
                                         uint32_t b0, uint32_t b1) {
    asm volatile(
        "mma.sync.aligned.m16n8k8.row.col.f32.tf32.tf32.f32 "
        "{%0,%1,%2,%3},{%4,%5,%6,%7},{%8,%9},{%0,%1,%2,%3};"
        : "+f"(d0), "+f"(d1), "+f"(d2), "+f"(d3)
        : "r"(a0), "r"(a1), "r"(a2), "r"(a3), "r"(b0), "r"(b1));
}
__device__ __forceinline__ void cp16(void* s, const float* g) {
    uint32_t sa = (uint32_t)__cvta_generic_to_shared(s);
    asm volatile("cp.async.cg.shared.global [%0], [%1], 16;\n" :: "r"(sa), "l"(g));
}

// ---- pre-kernel: pack W[c][o] into per-thread tf32 fragment quads ----
// packed float index t: j=t&3, lane=(t>>2)&31, ksi=(t>>7)&3, mb16=(t>>9)&15, kc=t>>13
// quad of (kc,mb16,ksi,lane): {W[k][m], W[k][m+8], W[k+4][m], W[k+4][m+8]}
__global__ void wpack_kernel(const float* __restrict__ W) {
    int t    = blockIdx.x * 256 + threadIdx.x;
    int j    = t & 3;
    int lane = (t >> 2) & 31;
    int ksi  = (t >> 7) & 3;
    int mb16 = (t >> 9) & 15;
    int kc   = t >> 13;
    int gid = lane >> 2, tig = lane & 3;
    int m = mb16 * 16 + gid + (j & 1) * 8;
    int k = kc * KB + ksi * 8 + tig + (j >> 1) * 4;
    g_Wp[t] = __uint_as_float(f2tf32(W[k * C_OUT + m]));
}

// ---- main kernel ----
__global__ void __launch_bounds__(512, 1)
conv_interleave_kernel(XPtrs xs, const float* __restrict__ bg, float* __restrict__ out)
{
    extern __shared__ char smem[];

    const int tid  = threadIdx.x;
    const int lane = tid & 31;
    const int warp = tid >> 5;        // 0..15
    const int gid  = lane >> 2;
    const int tig  = lane & 3;

    const int p0 = blockIdx.x * 128;
    const int z  = blockIdx.y;        // 0..23
    const int ii = z >> 1;
    const int bb = z & 1;
    const float* Xg = xs.p[ii] + (size_t)bb * (C_IN * PIXN);

    const int warp_m = (warp >> 2) * 64;    // out-channel base (0..192)
    const int wm16   = (warp >> 2) * 4;     // m16-block base
    const int warp_n = (warp & 3) * 32;     // pixel base (0..96)

    float d[4][4][4];
    #pragma unroll
    for (int mb = 0; mb < 4; ++mb)
        #pragma unroll
        for (int nb = 0; nb < 4; ++nb)
            #pragma unroll
            for (int r = 0; r < 4; ++r) d[mb][nb][r] = 0.0f;

    // ---- stage loader (512 threads) ----
    auto load_stage = [&](int ch) {
        const int st = ch % NSTAGE;
        char* wdst = smem + st * STAGE_B;
        char* xdst = wdst + W_STAGE;
        const float* wsrc = g_Wp + ch * (KB * C_OUT);
        #pragma unroll
        for (int it = 0; it < 4; ++it) {           // W: 2048 x 16B, linear
            int idx = it * 512 + tid;
            cp16(wdst + idx * 16, wsrc + idx * 4);
        }
        #pragma unroll
        for (int it = 0; it < 2; ++it) {           // X: 32 rows x 512B (row pad 544B)
            int idx = it * 512 + tid;
            int k = idx >> 5, q = idx & 31;
            cp16(xdst + k * (RPX * 4) + q * 16,
                 Xg + (size_t)(ch * KB + k) * PIXN + p0 + q * 4);
        }
        asm volatile("cp.async.commit_group;");
    };

    load_stage(0);
    load_stage(1);

    #pragma unroll 1
    for (int ch = 0; ch < NCHUNK; ++ch) {
        asm volatile("cp.async.wait_group 1;");
        __syncthreads();

        const int s = ch % NSTAGE;
        if (ch + 2 < NCHUNK) load_stage(ch + 2);

        const float4* Wf4 = (const float4*)(smem + s * STAGE_B);
        const float*  Xst = (const float*)(smem + s * STAGE_B + W_STAGE);

        #pragma unroll
        for (int ksi = 0; ksi < NKS; ++ksi) {
            const int kr = ksi * 8 + tig;

            // A fragments: packed tf32 quads, one LDS.128 per m16-block
            float4 aq[4];
            #pragma unroll
            for (int mb = 0; mb < 4; ++mb)
                aq[mb] = Wf4[((wm16 + mb) * 4 + ksi) * 32 + lane];

            // B fragments: conflict-free LDS.32 + cvt
            uint32_t bt[8];
            #pragma unroll
            for (int nb = 0; nb < 4; ++nb) {
                const int n = warp_n + nb * 8 + gid;
                bt[2 * nb]     = f2tf32(Xst[kr * RPX + n]);
                bt[2 * nb + 1] = f2tf32(Xst[(kr + 4) * RPX + n]);
            }

            #pragma unroll
            for (int mb = 0; mb < 4; ++mb) {
                const uint32_t a0 = __float_as_uint(aq[mb].x);
                const uint32_t a1 = __float_as_uint(aq[mb].y);
                const uint32_t a2 = __float_as_uint(aq[mb].z);
                const uint32_t a3 = __float_as_uint(aq[mb].w);
                #pragma unroll
                for (int nb = 0; nb < 4; ++nb)
                    mma_tf32(d[mb][nb][0], d[mb][nb][1], d[mb][nb][2], d[mb][nb][3],
                             a0, a1, a2, a3, bt[2 * nb], bt[2 * nb + 1]);
            }
        }
        __syncthreads();   // all warps done with stage s before refill
    }

    // ---- epilogue: interleaved scatter + bias*count ----
    #pragma unroll
    for (int mb = 0; mb < 4; ++mb) {
        const int o = warp_m + mb * 16 + gid;
        const float bv0 = __ldg(bg + o);
        const float bv1 = __ldg(bg + o + 8);
        #pragma unroll
        for (int nb = 0; nb < 4; ++nb) {
            const int p = p0 + warp_n + nb * 8 + 2 * tig;
            const int h = p >> 8;
            const int w = p & 255;
            const int r = 12 * h + ii;
            const int cnt = min(11, r) - max(0, r - (HOUTN - 12)) + 1;
            const float fc = (float)cnt;
            const float bias0 = bv0 * fc;
            const float bias1 = bv1 * fc;
            const size_t base = ((size_t)(bb * C_OUT + o) * HOUTN + r) * WwN + w;
            float2 v0 = make_float2(d[mb][nb][0] + bias0, d[mb][nb][1] + bias0);
            float2 v1 = make_float2(d[mb][nb][2] + bias1, d[mb][nb][3] + bias1);
            *reinterpret_cast<float2*>(out + base) = v0;
            *reinterpret_cast<float2*>(out + base + (size_t)8 * HOUTN * WwN) = v1;
        }
    }
}

extern "C" void kernel_launch(void* const* d_in, const int* in_sizes, int n_in,
                              void* d_out, int out_size)
{
    (void)in_sizes; (void)n_in; (void)out_size;

    XPtrs xs;
    for (int i = 0; i < 12; ++i) xs.p[i] = (const float*)d_in[i];
    const float* W = (const float*)d_in[12];
    const float* b = (const float*)d_in[13];
    float* out = (float*)d_out;

    wpack_kernel<<<256, 256>>>(W);

    cudaFuncSetAttribute(conv_interleave_kernel,
                         cudaFuncAttributeMaxDynamicSharedMemorySize, SMEM_BYTES);
    dim3 grid(PIXN / 128, 24, 1);   // 128 x 24 = 3072 CTAs
    conv_interleave_kernel<<<grid, 512, SMEM_BYTES>>>(xs, b, out);
}